// round 14
// baseline (speedup 1.0000x reference)
#include <cuda_runtime.h>
#include <cuda_bf16.h>
#include <math.h>

#define Tn 512
#define Vn 512
#define Fn 12
#define En 512
#define Hn 8
#define Dn 64
#define VFn (Vn*Fn)
#define Mbig (Vn*Tn)

// ---------------- mma.sync / ldmatrix macros (proven in R13) -----------------
#define LDSM_X4(r0, r1, r2, r3, addr) \
    asm volatile("ldmatrix.sync.aligned.m8n8.x4.shared.b16 {%0,%1,%2,%3}, [%4];" \
                 : "=r"(r0), "=r"(r1), "=r"(r2), "=r"(r3) : "r"(addr))
#define LDSM_X2(r0, r1, addr) \
    asm volatile("ldmatrix.sync.aligned.m8n8.x2.shared.b16 {%0,%1}, [%2];" \
                 : "=r"(r0), "=r"(r1) : "r"(addr))
#define MMA16816(d0, d1, d2, d3, a0, a1, a2, a3, b0, b1) \
    asm volatile("mma.sync.aligned.m16n8k16.row.col.f32.bf16.bf16.f32 " \
                 "{%0,%1,%2,%3}, {%4,%5,%6,%7}, {%8,%9}, {%0,%1,%2,%3};" \
                 : "+f"(d0), "+f"(d1), "+f"(d2), "+f"(d3) \
                 : "r"(a0), "r"(a1), "r"(a2), "r"(a3), "r"(b0), "r"(b1))

// split float4 into bf16 hi/lo pairs and store to GLOBAL hi/lo arrays at base
#define SPLIT_STORE_G(dsthi, dstlo, base, v) do { \
    __nv_bfloat16 h0 = __float2bfloat16((v).x); \
    __nv_bfloat16 h1 = __float2bfloat16((v).y); \
    __nv_bfloat16 h2 = __float2bfloat16((v).z); \
    __nv_bfloat16 h3 = __float2bfloat16((v).w); \
    __nv_bfloat16 l0 = __float2bfloat16((v).x - __bfloat162float(h0)); \
    __nv_bfloat16 l1 = __float2bfloat16((v).y - __bfloat162float(h1)); \
    __nv_bfloat16 l2 = __float2bfloat16((v).z - __bfloat162float(h2)); \
    __nv_bfloat16 l3 = __float2bfloat16((v).w - __bfloat162float(h3)); \
    __nv_bfloat162 hp0; hp0.x = h0; hp0.y = h1; \
    __nv_bfloat162 hp1; hp1.x = h2; hp1.y = h3; \
    __nv_bfloat162 lp0; lp0.x = l0; lp0.y = l1; \
    __nv_bfloat162 lp1; lp1.x = l2; lp1.y = l3; \
    *(__nv_bfloat162*)(&(dsthi)[(base)])     = hp0; \
    *(__nv_bfloat162*)(&(dsthi)[(base) + 2]) = hp1; \
    *(__nv_bfloat162*)(&(dstlo)[(base)])     = lp0; \
    *(__nv_bfloat162*)(&(dstlo)[(base) + 2]) = lp1; \
} while (0)

// dynamic-smem: 4 regions x 2 stages x (128 rows * 24 bf16) = 49152 bytes
#define STAGE_ELEMS (128 * 24)
#define MGEMM_SMEM  (4 * 2 * STAGE_ELEMS * 2)

// ---------------- scratch (~1.06 GB) ----------------------------------------
static __device__ __nv_bfloat16 g_tln_hi[Tn*En], g_tln_lo[Tn*En];
static __device__ __nv_bfloat16 g_vln_hi[VFn*En], g_vln_lo[VFn*En];
static __device__ float g_q[Tn*En];
static __device__ float g_k[VFn*En];
static __device__ float g_v[VFn*En];
static __device__ __nv_bfloat16 g_ahi[(size_t)Mbig*En];   // 256 MB (attn out, then LN2 out)
static __device__ __nv_bfloat16 g_alo[(size_t)Mbig*En];   // 256 MB
static __device__ float g_o[(size_t)Mbig*En];             // 512 MB
static __device__ __nv_bfloat16 g_w_hi[5][En*En], g_w_lo[5][En*En];

// ---------------- LayerNorm fp32-out (LN3) ----------------------------------
__global__ __launch_bounds__(128) void ln_kernel(
    const float* __restrict__ x, const float* __restrict__ g,
    const float* __restrict__ b, float* __restrict__ out)
{
    int row = blockIdx.x;
    int tid = threadIdx.x;
    float4 v = ((const float4*)(x + (size_t)row * En))[tid];
    float s  = v.x + v.y + v.z + v.w;
    float ss = v.x*v.x + v.y*v.y + v.z*v.z + v.w*v.w;
    #pragma unroll
    for (int o = 16; o > 0; o >>= 1) {
        s  += __shfl_xor_sync(0xffffffffu, s,  o);
        ss += __shfl_xor_sync(0xffffffffu, ss, o);
    }
    __shared__ float sm[4], sm2[4];
    int w = tid >> 5, l = tid & 31;
    if (l == 0) { sm[w] = s; sm2[w] = ss; }
    __syncthreads();
    s  = sm[0] + sm[1] + sm[2] + sm[3];
    ss = sm2[0] + sm2[1] + sm2[2] + sm2[3];
    float mean = s * (1.0f / En);
    float rstd = rsqrtf(ss * (1.0f / En) - mean * mean + 1e-5f);
    float4 gg = ((const float4*)g)[tid];
    float4 bb = ((const float4*)b)[tid];
    float4 o;
    o.x = (v.x - mean) * rstd * gg.x + bb.x;
    o.y = (v.y - mean) * rstd * gg.y + bb.y;
    o.z = (v.z - mean) * rstd * gg.z + bb.z;
    o.w = (v.w - mean) * rstd * gg.w + bb.w;
    ((float4*)(out + (size_t)row * En))[tid] = o;
}

// ---------------- LayerNorm emitting bf16 hi/lo ------------------------------
__global__ __launch_bounds__(128) void ln_split_kernel(
    const float* __restrict__ x, const float* __restrict__ g,
    const float* __restrict__ b,
    __nv_bfloat16* __restrict__ ohi, __nv_bfloat16* __restrict__ olo)
{
    int row = blockIdx.x;
    int tid = threadIdx.x;
    float4 v = ((const float4*)(x + (size_t)row * En))[tid];
    float s  = v.x + v.y + v.z + v.w;
    float ss = v.x*v.x + v.y*v.y + v.z*v.z + v.w*v.w;
    #pragma unroll
    for (int o = 16; o > 0; o >>= 1) {
        s  += __shfl_xor_sync(0xffffffffu, s,  o);
        ss += __shfl_xor_sync(0xffffffffu, ss, o);
    }
    __shared__ float sm[4], sm2[4];
    int w = tid >> 5, l = tid & 31;
    if (l == 0) { sm[w] = s; sm2[w] = ss; }
    __syncthreads();
    s  = sm[0] + sm[1] + sm[2] + sm[3];
    ss = sm2[0] + sm2[1] + sm2[2] + sm2[3];
    float mean = s * (1.0f / En);
    float rstd = rsqrtf(ss * (1.0f / En) - mean * mean + 1e-5f);
    float4 gg = ((const float4*)g)[tid];
    float4 bb = ((const float4*)b)[tid];
    float4 o;
    o.x = (v.x - mean) * rstd * gg.x + bb.x;
    o.y = (v.y - mean) * rstd * gg.y + bb.y;
    o.z = (v.z - mean) * rstd * gg.z + bb.z;
    o.w = (v.w - mean) * rstd * gg.w + bb.w;
    size_t base = (size_t)row * En + tid * 4;
    SPLIT_STORE_G(ohi, olo, base, o);
}

// ---------------- weight fp32 -> bf16 hi/lo ----------------------------------
__global__ __launch_bounds__(128) void w_convert_kernel(
    const float* __restrict__ src,
    __nv_bfloat16* __restrict__ hi, __nv_bfloat16* __restrict__ lo)
{
    int row = blockIdx.x;
    int tid = threadIdx.x;
    float4 v = ((const float4*)(src + (size_t)row * En))[tid];
    size_t base = (size_t)row * En + tid * 4;
    SPLIT_STORE_G(hi, lo, base, v);
}

// ---------------- tensor-core GEMM, pre-split bf16 operands ------------------
// C[M,512] = (Ahi+Alo) @ (Whi+Wlo)^T + bias  (+ (Rhi+Rlo) residual if ADD)
// CTA 128x128, 8 warps 4x2 (warp 32x64), BK=16, double-buffered dynamic smem.
// Staging = pure uint4 copies (no cvt). 3-term split: ah*bh + ah*bl + al*bh.
template<bool ADD>
__global__ __launch_bounds__(256, 2) void mgemm_kernel(
    const __nv_bfloat16* __restrict__ Ahi, const __nv_bfloat16* __restrict__ Alo,
    const __nv_bfloat16* __restrict__ Whi, const __nv_bfloat16* __restrict__ Wlo,
    const float* __restrict__ bias,
    const __nv_bfloat16* __restrict__ Rhi, const __nv_bfloat16* __restrict__ Rlo,
    float* __restrict__ C)
{
    extern __shared__ __align__(16) char dynsm[];
    __nv_bfloat16* sAhi = (__nv_bfloat16*)(dynsm);
    __nv_bfloat16* sAlo = sAhi + 2 * STAGE_ELEMS;
    __nv_bfloat16* sWhi = sAlo + 2 * STAGE_ELEMS;
    __nv_bfloat16* sWlo = sWhi + 2 * STAGE_ELEMS;

    int tid = threadIdx.x;
    int wid = tid >> 5, lane = tid & 31;
    int bm = blockIdx.x, bn = blockIdx.y;
    int warp_m = (wid >> 1) * 32;
    int warp_n = (wid & 1) * 64;

    const __nv_bfloat16* AhiB = Ahi + (size_t)bm * 128 * 512;
    const __nv_bfloat16* AloB = Alo + (size_t)bm * 128 * 512;
    const __nv_bfloat16* WhiB = Whi + (size_t)bn * 128 * 512;
    const __nv_bfloat16* WloB = Wlo + (size_t)bn * 128 * 512;

    float acc[2][8][4];
    #pragma unroll
    for (int im = 0; im < 2; im++)
        #pragma unroll
        for (int jn = 0; jn < 8; jn++)
            #pragma unroll
            for (int e = 0; e < 4; e++) acc[im][jn][e] = 0.0f;

    int r2 = tid >> 1;          // 0..127 row
    int c2 = (tid & 1) * 8;     // 0 or 8 (bf16 elems)
    int soff = r2 * 24 + c2;
    size_t goff = (size_t)r2 * 512 + c2;

    // stage chunk 0 -> buffer 0 (pure copies)
    *(uint4*)&sAhi[soff] = *(const uint4*)&AhiB[goff];
    *(uint4*)&sAlo[soff] = *(const uint4*)&AloB[goff];
    *(uint4*)&sWhi[soff] = *(const uint4*)&WhiB[goff];
    *(uint4*)&sWlo[soff] = *(const uint4*)&WloB[goff];
    __syncthreads();

    uint4 pah, pal, pwh, pwl;
    for (int kt = 0; kt < 32; kt++) {
        int cur = kt & 1;
        if (kt + 1 < 32) {
            size_t g = goff + (size_t)(kt + 1) * 16;
            pah = *(const uint4*)&AhiB[g];
            pal = *(const uint4*)&AloB[g];
            pwh = *(const uint4*)&WhiB[g];
            pwl = *(const uint4*)&WloB[g];
        }

        unsigned aHi = (unsigned)__cvta_generic_to_shared(sAhi + cur * STAGE_ELEMS);
        unsigned aLo = (unsigned)__cvta_generic_to_shared(sAlo + cur * STAGE_ELEMS);
        unsigned wHi = (unsigned)__cvta_generic_to_shared(sWhi + cur * STAGE_ELEMS);
        unsigned wLo = (unsigned)__cvta_generic_to_shared(sWlo + cur * STAGE_ELEMS);

        unsigned ah[2][4], al[2][4], bh[8][2], bl[8][2];
        #pragma unroll
        for (int im = 0; im < 2; im++) {
            unsigned off = ((unsigned)(warp_m + im * 16 + (lane & 15)) * 24u
                            + (((unsigned)lane >> 4) << 3)) * 2u;
            LDSM_X4(ah[im][0], ah[im][1], ah[im][2], ah[im][3], aHi + off);
            LDSM_X4(al[im][0], al[im][1], al[im][2], al[im][3], aLo + off);
        }
        #pragma unroll
        for (int jn = 0; jn < 8; jn++) {
            unsigned off = ((unsigned)(warp_n + jn * 8 + (lane & 7)) * 24u
                            + ((((unsigned)lane >> 3) & 1u) << 3)) * 2u;
            LDSM_X2(bh[jn][0], bh[jn][1], wHi + off);
            LDSM_X2(bl[jn][0], bl[jn][1], wLo + off);
        }

        #pragma unroll
        for (int im = 0; im < 2; im++) {
            #pragma unroll
            for (int jn = 0; jn < 8; jn++) {
                MMA16816(acc[im][jn][0], acc[im][jn][1], acc[im][jn][2], acc[im][jn][3],
                         ah[im][0], ah[im][1], ah[im][2], ah[im][3],
                         bh[jn][0], bh[jn][1]);
                MMA16816(acc[im][jn][0], acc[im][jn][1], acc[im][jn][2], acc[im][jn][3],
                         ah[im][0], ah[im][1], ah[im][2], ah[im][3],
                         bl[jn][0], bl[jn][1]);
                MMA16816(acc[im][jn][0], acc[im][jn][1], acc[im][jn][2], acc[im][jn][3],
                         al[im][0], al[im][1], al[im][2], al[im][3],
                         bh[jn][0], bh[jn][1]);
            }
        }

        if (kt + 1 < 32) {
            __syncthreads();
            int nb = cur ^ 1;
            *(uint4*)&sAhi[nb * STAGE_ELEMS + soff] = pah;
            *(uint4*)&sAlo[nb * STAGE_ELEMS + soff] = pal;
            *(uint4*)&sWhi[nb * STAGE_ELEMS + soff] = pwh;
            *(uint4*)&sWlo[nb * STAGE_ELEMS + soff] = pwl;
            __syncthreads();
        }
    }

    // epilogue
    #pragma unroll
    for (int im = 0; im < 2; im++) {
        #pragma unroll
        for (int jn = 0; jn < 8; jn++) {
            int gr = bm * 128 + warp_m + im * 16 + (lane >> 2);
            int gc = bn * 128 + warp_n + jn * 8 + (lane & 3) * 2;
            float2 b2 = *(const float2*)(bias + gc);
            size_t base0 = (size_t)gr * 512 + gc;
            size_t base1 = (size_t)(gr + 8) * 512 + gc;
            float2 v0, v1;
            v0.x = acc[im][jn][0] + b2.x; v0.y = acc[im][jn][1] + b2.y;
            v1.x = acc[im][jn][2] + b2.x; v1.y = acc[im][jn][3] + b2.y;
            if (ADD) {
                __nv_bfloat162 h0 = *(const __nv_bfloat162*)(Rhi + base0);
                __nv_bfloat162 l0 = *(const __nv_bfloat162*)(Rlo + base0);
                __nv_bfloat162 h1 = *(const __nv_bfloat162*)(Rhi + base1);
                __nv_bfloat162 l1 = *(const __nv_bfloat162*)(Rlo + base1);
                v0.x += __bfloat162float(h0.x) + __bfloat162float(l0.x);
                v0.y += __bfloat162float(h0.y) + __bfloat162float(l0.y);
                v1.x += __bfloat162float(h1.x) + __bfloat162float(l1.x);
                v1.y += __bfloat162float(h1.y) + __bfloat162float(l1.y);
            }
            *(float2*)(C + base0) = v0;
            *(float2*)(C + base1) = v1;
        }
    }
}

// ---------------- fused attention (fp32 math, bf16 hi/lo output) -------------
__global__ __launch_bounds__(256) void attn_kernel(
    const float* __restrict__ q, const float* __restrict__ kk,
    const float* __restrict__ vv,
    __nv_bfloat16* __restrict__ ahi, __nv_bfloat16* __restrict__ alo)
{
    extern __shared__ float smem[];
    float* k_s = smem;
    float* v_s = smem + Fn * En;
    float* w_s = smem + 2 * Fn * En;

    int vb  = blockIdx.x;
    int tt  = blockIdx.y;
    int tid = threadIdx.x;

    {
        const float4* kg = (const float4*)(kk + (size_t)vb * Fn * En);
        const float4* vg = (const float4*)(vv + (size_t)vb * Fn * En);
        float4* k4 = (float4*)k_s;
        float4* v4 = (float4*)v_s;
        for (int i = tid; i < Fn * En / 4; i += 256) { k4[i] = kg[i]; v4[i] = vg[i]; }
    }
    __syncthreads();

    int h = tid >> 5, lane = tid & 31;
    int tbase = tt * 128 + lane * 4;

    float acc[Fn][4];
    #pragma unroll
    for (int f = 0; f < Fn; f++)
        #pragma unroll
        for (int i = 0; i < 4; i++) acc[f][i] = 0.0f;

    const float* q0 = q + (size_t)(tbase + 0) * En + h * Dn;
    const float* q1 = q + (size_t)(tbase + 1) * En + h * Dn;
    const float* q2 = q + (size_t)(tbase + 2) * En + h * Dn;
    const float* q3 = q + (size_t)(tbase + 3) * En + h * Dn;
    const float* kb = k_s + h * Dn;

    for (int dc = 0; dc < Dn; dc += 8) {
        float qf[4][8];
        *(float4*)&qf[0][0] = *(const float4*)(q0 + dc);
        *(float4*)&qf[0][4] = *(const float4*)(q0 + dc + 4);
        *(float4*)&qf[1][0] = *(const float4*)(q1 + dc);
        *(float4*)&qf[1][4] = *(const float4*)(q1 + dc + 4);
        *(float4*)&qf[2][0] = *(const float4*)(q2 + dc);
        *(float4*)&qf[2][4] = *(const float4*)(q2 + dc + 4);
        *(float4*)&qf[3][0] = *(const float4*)(q3 + dc);
        *(float4*)&qf[3][4] = *(const float4*)(q3 + dc + 4);
        #pragma unroll
        for (int d = 0; d < 8; d++) {
            #pragma unroll
            for (int f = 0; f < Fn; f++) {
                float kv = kb[f * En + dc + d];
                #pragma unroll
                for (int i = 0; i < 4; i++)
                    acc[f][i] = fmaf(kv, qf[i][d], acc[f][i]);
            }
        }
    }

    const float scale = 0.125f;
    #pragma unroll
    for (int i = 0; i < 4; i++) {
        float m = -1e30f;
        #pragma unroll
        for (int f = 0; f < Fn; f++) m = fmaxf(m, acc[f][i] * scale);
        float e[Fn];
        float s = 0.0f;
        #pragma unroll
        for (int f = 0; f < Fn; f++) { e[f] = __expf(acc[f][i] * scale - m); s += e[f]; }
        float inv = 1.0f / s;
        #pragma unroll
        for (int f = 0; f < Fn; f++)
            w_s[(h * Fn + f) * 128 + lane * 4 + i] = e[f] * inv;
    }
    __syncthreads();

    int ec   = tid & 127;
    int half = tid >> 7;
    int e0   = ec * 4;
    int hh   = e0 >> 6;
    #pragma unroll 4
    for (int tl = 0; tl < 64; tl++) {
        int t_local = half * 64 + tl;
        float4 o = make_float4(0.f, 0.f, 0.f, 0.f);
        #pragma unroll
        for (int f = 0; f < Fn; f++) {
            float w   = w_s[(hh * Fn + f) * 128 + t_local];
            float4 vq = *(const float4*)&v_s[f * En + e0];
            o.x = fmaf(w, vq.x, o.x);
            o.y = fmaf(w, vq.y, o.y);
            o.z = fmaf(w, vq.z, o.z);
            o.w = fmaf(w, vq.w, o.w);
        }
        size_t t = (size_t)tt * 128 + t_local;
        size_t base = ((size_t)vb * Tn + t) * En + e0;
        SPLIT_STORE_G(ahi, alo, base, o);
    }
}

// ---------------- launch ------------------------------------------------------
extern "C" void kernel_launch(void* const* d_in, const int* in_sizes, int n_in,
                              void* d_out, int out_size)
{
    const float* text  = (const float*)d_in[0];
    const float* video = (const float*)d_in[1];
    const float* W[5]  = { (const float*)d_in[2], (const float*)d_in[4],
                           (const float*)d_in[6], (const float*)d_in[8],
                           (const float*)d_in[10] };
    const float* bq = (const float*)d_in[3];
    const float* bk = (const float*)d_in[5];
    const float* bv = (const float*)d_in[7];
    const float* bo = (const float*)d_in[9];
    const float* bl = (const float*)d_in[11];
    const float* ln1g = (const float*)d_in[12]; const float* ln1b = (const float*)d_in[13];
    const float* ln2g = (const float*)d_in[14]; const float* ln2b = (const float*)d_in[15];
    const float* ln3g = (const float*)d_in[16]; const float* ln3b = (const float*)d_in[17];
    float* out = (float*)d_out;

    __nv_bfloat16 *tln_hi, *tln_lo, *vln_hi, *vln_lo, *ahi, *alo, *w_hi, *w_lo;
    float *q, *k, *v, *o;
    cudaGetSymbolAddress((void**)&tln_hi, g_tln_hi);
    cudaGetSymbolAddress((void**)&tln_lo, g_tln_lo);
    cudaGetSymbolAddress((void**)&vln_hi, g_vln_hi);
    cudaGetSymbolAddress((void**)&vln_lo, g_vln_lo);
    cudaGetSymbolAddress((void**)&q,   g_q);
    cudaGetSymbolAddress((void**)&k,   g_k);
    cudaGetSymbolAddress((void**)&v,   g_v);
    cudaGetSymbolAddress((void**)&ahi, g_ahi);
    cudaGetSymbolAddress((void**)&alo, g_alo);
    cudaGetSymbolAddress((void**)&o,   g_o);
    cudaGetSymbolAddress((void**)&w_hi, g_w_hi);
    cudaGetSymbolAddress((void**)&w_lo, g_w_lo);

    cudaFuncSetAttribute(mgemm_kernel<false>, cudaFuncAttributeMaxDynamicSharedMemorySize, MGEMM_SMEM);
    cudaFuncSetAttribute(mgemm_kernel<true>,  cudaFuncAttributeMaxDynamicSharedMemorySize, MGEMM_SMEM);
    cudaFuncSetAttribute(attn_kernel, cudaFuncAttributeMaxDynamicSharedMemorySize, 98304);

    // weight pre-split (tiny)
    for (int i = 0; i < 5; i++)
        w_convert_kernel<<<En, 128>>>(W[i], w_hi + (size_t)i * En * En, w_lo + (size_t)i * En * En);

    // LN1 -> bf16 hi/lo
    ln_split_kernel<<<Tn, 128>>>(text, ln1g, ln1b, tln_hi, tln_lo);
    ln_split_kernel<<<VFn, 128>>>(video, ln1g, ln1b, vln_hi, vln_lo);

    // projections
    mgemm_kernel<false><<<dim3(Tn / 128, 4), 256, MGEMM_SMEM>>>(
        tln_hi, tln_lo, w_hi + 0*(size_t)En*En, w_lo + 0*(size_t)En*En, bq, nullptr, nullptr, q);
    mgemm_kernel<false><<<dim3(VFn / 128, 4), 256, MGEMM_SMEM>>>(
        vln_hi, vln_lo, w_hi + 1*(size_t)En*En, w_lo + 1*(size_t)En*En, bk, nullptr, nullptr, k);
    mgemm_kernel<false><<<dim3(VFn / 128, 4), 256, MGEMM_SMEM>>>(
        vln_hi, vln_lo, w_hi + 2*(size_t)En*En, w_lo + 2*(size_t)En*En, bv, nullptr, nullptr, v);

    // fused attention -> bf16 hi/lo (GEMM1's A)
    attn_kernel<<<dim3(Vn, 4), 256, 98304>>>(q, k, v, ahi, alo);

    // o = attn @ Wo^T + bo
    mgemm_kernel<false><<<dim3(Mbig / 128, 4), 256, MGEMM_SMEM>>>(
        ahi, alo, w_hi + 3*(size_t)En*En, w_lo + 3*(size_t)En*En, bo, nullptr, nullptr, o);

    // LN2 -> bf16 hi/lo (reuses ahi/alo, dead after GEMM1)
    ln_split_kernel<<<Mbig, 128>>>(o, ln2g, ln2b, ahi, alo);

    // out_pre = ln2out @ Wl^T + bl + ln2out (residual reconstructed hi+lo)
    mgemm_kernel<true><<<dim3(Mbig / 128, 4), 256, MGEMM_SMEM>>>(
        ahi, alo, w_hi + 4*(size_t)En*En, w_lo + 4*(size_t)En*En, bl, ahi, alo, out);

    // LN3 in-place
    ln_kernel<<<Mbig, 128>>>(out, ln3g, ln3b, out);
}